// round 4
// baseline (speedup 1.0000x reference)
#include <cuda_runtime.h>
#include <cuda_fp16.h>
#include <cstdint>

// out[B,256] = (x[B,128] @ W[256,128]^T + bias)^2
// fp16 2-term split (x = xh + xl, w fp16), W fragments register-persistent.
// 256 thr/CTA, TILE_M=64, warp grid 2m x 4n. A double-buffered in smem.

#define DDIM   128
#define ODIM   256
#define TILE_M 64
#define NTILES 2048
#define GRID   148

// smem (bytes): W staging [0,65536) aliased by A buffers after init.
#define SM_A0    0
#define SM_A1    32768
#define ALO      16384          // lo-term offset within an A buffer
#define SM_W     0
#define SM_BIAS  65536
#define SM_TOTAL 66592

static __device__ __forceinline__ uint32_t smem_u32(const void* p) {
    uint32_t a;
    asm("{ .reg .u64 t; cvta.to.shared.u64 t, %1; cvt.u32.u64 %0, t; }" : "=r"(a) : "l"(p));
    return a;
}

static __device__ __forceinline__ void ldsm4(uint32_t* r, uint32_t a) {
    asm volatile("ldmatrix.sync.aligned.m8n8.x4.shared.b16 {%0,%1,%2,%3}, [%4];"
                 : "=r"(r[0]), "=r"(r[1]), "=r"(r[2]), "=r"(r[3]) : "r"(a));
}

static __device__ __forceinline__ void sts64(uint32_t a, uint32_t v0, uint32_t v1) {
    asm volatile("st.shared.v2.b32 [%0], {%1, %2};" :: "r"(a), "r"(v0), "r"(v1));
}

static __device__ __forceinline__ void mma_f16(float* d, const uint32_t* a,
                                               uint32_t b0, uint32_t b1) {
    asm volatile(
        "mma.sync.aligned.m16n8k16.row.col.f32.f16.f16.f32 "
        "{%0,%1,%2,%3}, {%4,%5,%6,%7}, {%8,%9}, {%0,%1,%2,%3};"
        : "+f"(d[0]), "+f"(d[1]), "+f"(d[2]), "+f"(d[3])
        : "r"(a[0]), "r"(a[1]), "r"(a[2]), "r"(a[3]), "r"(b0), "r"(b1));
}

// fp32 pair -> packed fp16 hi pair + packed fp16 residual pair
static __device__ __forceinline__ void splitf16(float x, float y, uint32_t& h, uint32_t& l) {
    __half2 hp;
    asm("cvt.rn.f16x2.f32 %0, %1, %2;" : "=r"(*(uint32_t*)&hp) : "f"(y), "f"(x));
    float rx = x - __half2float(hp.x);
    float ry = y - __half2float(hp.y);
    h = *reinterpret_cast<uint32_t*>(&hp);
    asm("cvt.rn.f16x2.f32 %0, %1, %2;" : "=r"(l) : "f"(ry), "f"(rx));
}

// convert one staged float4 (flat float4-index of a 64x128 tile) into A buffer
static __device__ __forceinline__ void cvt_sts_x(uint32_t xb, int idx4, float4 v) {
    const int row = idx4 >> 5;          // 0..63
    const int cg  = idx4 & 31;
    uint32_t h0, l0, h1, l1;
    splitf16(v.x, v.y, h0, l0);
    splitf16(v.z, v.w, h1, l1);
    const uint32_t a = xb + (uint32_t)row * 256 +
                       ((uint32_t)(((cg >> 1) ^ (row & 7)) << 4)) + ((cg & 1) << 3);
    sts64(a, h0, h1);
    sts64(a + ALO, l0, l1);
}

__global__ void __launch_bounds__(256, 1)
hyper_kernel(const float* __restrict__ xg, const float* __restrict__ wg,
             const float* __restrict__ bg, float* __restrict__ out) {
    extern __shared__ __align__(16) char smem[];
    const uint32_t sb = smem_u32(smem);
    const int tid  = threadIdx.x;
    const int lane = tid & 31;
    const int wid  = tid >> 5;
    const int wm   = wid >> 2;           // 0..1 : rows wm*32 .. +31
    const int wn   = wid & 3;            // 0..3 : cols wn*64 .. +63
    const int bid  = blockIdx.x;

    // bias -> smem
    reinterpret_cast<float*>(smem + SM_BIAS)[tid] = bg[tid];

    const float4* xg4 = reinterpret_cast<const float4*>(xg);

    // prefetch tile 0 (overlaps W init)
    float4 st0[8];
    {
        const size_t b4 = (size_t)bid * (TILE_M * 32);
        #pragma unroll
        for (int it = 0; it < 8; it++) st0[it] = xg4[b4 + tid + it * 256];
    }

    // W: fp32 -> fp16, swizzled staging in smem [n][k] 256B rows
    {
        const float4* w4 = reinterpret_cast<const float4*>(wg);
        #pragma unroll 4
        for (int i = tid; i < ODIM * 32; i += 256) {
            const int n  = i >> 5;
            const int cg = i & 31;
            float4 v = w4[i];
            __half2 p0, p1;
            asm("cvt.rn.f16x2.f32 %0, %1, %2;" : "=r"(*(uint32_t*)&p0) : "f"(v.y), "f"(v.x));
            asm("cvt.rn.f16x2.f32 %0, %1, %2;" : "=r"(*(uint32_t*)&p1) : "f"(v.w), "f"(v.z));
            const uint32_t a = sb + SM_W + (uint32_t)n * 256 +
                               ((uint32_t)(((cg >> 1) ^ (n & 7)) << 4)) + ((cg & 1) << 3);
            sts64(a, *reinterpret_cast<uint32_t*>(&p0), *reinterpret_cast<uint32_t*>(&p1));
        }
    }
    __syncthreads();

    // ---- B fragments -> registers (persistent, never reloaded) ----
    const uint32_t lx  = (uint32_t)(lane & 7);
    const uint32_t khA = (uint32_t)((lane >> 4) & 1);
    const uint32_t khB = (uint32_t)((lane >> 3) & 1);
    uint32_t breg[8][8][2];
    {
        const uint32_t preB = sb + SM_W +
            (uint32_t)(wn * 64 + (lane & 7) + ((lane & 16) ? 8 : 0)) * 256;
        #pragma unroll
        for (int ks = 0; ks < 8; ks++) {
            const uint32_t swB = ((((uint32_t)ks << 1) | khB) ^ lx) << 4;
            #pragma unroll
            for (int np = 0; np < 4; np++) {
                uint32_t t[4];
                ldsm4(t, preB + ((uint32_t)np << 12) + swB);
                breg[ks][2 * np][0]     = t[0];
                breg[ks][2 * np][1]     = t[1];
                breg[ks][2 * np + 1][0] = t[2];
                breg[ks][2 * np + 1][1] = t[3];
            }
        }
    }
    __syncthreads();   // all warps done reading W before A buffers overwrite it

    // tile 0 -> A buffer 0
    #pragma unroll
    for (int it = 0; it < 8; it++) cvt_sts_x(sb + SM_A0, tid + it * 256, st0[it]);
    __syncthreads();

    float acc[2][8][4];
    #pragma unroll
    for (int mt = 0; mt < 2; mt++)
        #pragma unroll
        for (int nt = 0; nt < 8; nt++)
            #pragma unroll
            for (int q = 0; q < 4; q++) acc[mt][nt][q] = 0.0f;

    const uint32_t arow_off =
        (uint32_t)(wm * 32 + (lane & 7) + ((lane & 8) ? 8 : 0)) * 256;
    const float* bs = reinterpret_cast<const float*>(smem + SM_BIAS);
    const int my_n = (NTILES - bid + GRID - 1) / GRID;

    for (int tt = 0; tt < my_n; tt++) {
        const int tile = bid + tt * GRID;
        const uint32_t xb  = sb + ((tt & 1) ? SM_A1 : SM_A0);
        const uint32_t nxb = sb + ((tt & 1) ? SM_A0 : SM_A1);
        const bool more = (tt + 1 < my_n);
        const size_t nb4 = more ? ((size_t)(tile + GRID) * (TILE_M * 32)) : 0;

        float4 s0[4];
        if (more) {
            #pragma unroll
            for (int it = 0; it < 4; it++) s0[it] = xg4[nb4 + tid + it * 256];
        }

        #pragma unroll
        for (int ks = 0; ks < 4; ks++) {
            const uint32_t swA = ((((uint32_t)ks << 1) | khA) ^ lx) << 4;
            uint32_t ah[2][4], al[2][4];
            ldsm4(ah[0], xb + arow_off + swA);
            ldsm4(ah[1], xb + arow_off + 4096 + swA);
            ldsm4(al[0], xb + ALO + arow_off + swA);
            ldsm4(al[1], xb + ALO + arow_off + 4096 + swA);
            #pragma unroll
            for (int np = 0; np < 4; np++) {
                #pragma unroll
                for (int mt = 0; mt < 2; mt++) {
                    mma_f16(acc[mt][2 * np],     ah[mt], breg[ks][2 * np][0],     breg[ks][2 * np][1]);
                    mma_f16(acc[mt][2 * np],     al[mt], breg[ks][2 * np][0],     breg[ks][2 * np][1]);
                    mma_f16(acc[mt][2 * np + 1], ah[mt], breg[ks][2 * np + 1][0], breg[ks][2 * np + 1][1]);
                    mma_f16(acc[mt][2 * np + 1], al[mt], breg[ks][2 * np + 1][0], breg[ks][2 * np + 1][1]);
                }
            }
        }

        float4 s1[4];
        if (more) {
            #pragma unroll
            for (int it = 0; it < 4; it++) cvt_sts_x(nxb, tid + it * 256, s0[it]);
            #pragma unroll
            for (int it = 0; it < 4; it++) s1[it] = xg4[nb4 + 1024 + tid + it * 256];
        }

        #pragma unroll
        for (int ks = 4; ks < 8; ks++) {
            const uint32_t swA = ((((uint32_t)ks << 1) | khA) ^ lx) << 4;
            uint32_t ah[2][4], al[2][4];
            ldsm4(ah[0], xb + arow_off + swA);
            ldsm4(ah[1], xb + arow_off + 4096 + swA);
            ldsm4(al[0], xb + ALO + arow_off + swA);
            ldsm4(al[1], xb + ALO + arow_off + 4096 + swA);
            #pragma unroll
            for (int np = 0; np < 4; np++) {
                #pragma unroll
                for (int mt = 0; mt < 2; mt++) {
                    mma_f16(acc[mt][2 * np],     ah[mt], breg[ks][2 * np][0],     breg[ks][2 * np][1]);
                    mma_f16(acc[mt][2 * np],     al[mt], breg[ks][2 * np][0],     breg[ks][2 * np][1]);
                    mma_f16(acc[mt][2 * np + 1], ah[mt], breg[ks][2 * np + 1][0], breg[ks][2 * np + 1][1]);
                    mma_f16(acc[mt][2 * np + 1], al[mt], breg[ks][2 * np + 1][0], breg[ks][2 * np + 1][1]);
                }
            }
        }

        if (more) {
            #pragma unroll
            for (int it = 0; it < 4; it++) cvt_sts_x(nxb, 1024 + tid + it * 256, s1[it]);
        }

        // epilogue: add bias, square, store; zero acc
        {
            const size_t m0 = (size_t)tile * TILE_M;
            #pragma unroll
            for (int mt = 0; mt < 2; mt++) {
                const size_t rr = m0 + (size_t)(wm * 32 + mt * 16 + (lane >> 2));
                #pragma unroll
                for (int nt = 0; nt < 8; nt++) {
                    const int cc = wn * 64 + nt * 8 + (lane & 3) * 2;
                    float2 bv = *reinterpret_cast<const float2*>(bs + cc);
                    float z0 = acc[mt][nt][0] + bv.x;
                    float z1 = acc[mt][nt][1] + bv.y;
                    float z2 = acc[mt][nt][2] + bv.x;
                    float z3 = acc[mt][nt][3] + bv.y;
                    float2 o0, o1;
                    o0.x = z0 * z0; o0.y = z1 * z1;
                    o1.x = z2 * z2; o1.y = z3 * z3;
                    *reinterpret_cast<float2*>(out + rr * ODIM + cc) = o0;
                    *reinterpret_cast<float2*>(out + (rr + 8) * ODIM + cc) = o1;
                    acc[mt][nt][0] = 0.0f; acc[mt][nt][1] = 0.0f;
                    acc[mt][nt][2] = 0.0f; acc[mt][nt][3] = 0.0f;
                }
            }
        }

        __syncthreads();
    }
}

extern "C" void kernel_launch(void* const* d_in, const int* in_sizes, int n_in,
                              void* d_out, int out_size) {
    const float* x = (const float*)d_in[0];
    const float* w = (const float*)d_in[1];
    const float* b = (const float*)d_in[2];
    float* out = (float*)d_out;

    cudaFuncSetAttribute(hyper_kernel, cudaFuncAttributeMaxDynamicSharedMemorySize, SM_TOTAL);
    hyper_kernel<<<GRID, 256, SM_TOTAL>>>(x, w, b, out);
}

// round 5
// speedup vs baseline: 1.2145x; 1.2145x over previous
#include <cuda_runtime.h>
#include <cuda_fp16.h>
#include <cstdint>

// out[B,256] = (x[B,128] @ W[256,128]^T + bias)^2
// Single-term fp16 mma.sync GEMM (x, w both rounded to fp16; fp32 accum).
// Error calibrated from round 3: ~3.5e-4 global rel err, threshold 1e-3.
// W fragments register-persistent; A double-buffered in smem.

#define DDIM   128
#define ODIM   256
#define TILE_M 64
#define NTILES 2048
#define GRID   148

// smem (bytes): W staging [0,65536) aliased by A buffers after init.
#define SM_A0    0
#define SM_A1    16384
#define SM_W     0
#define SM_BIAS  65536
#define SM_TOTAL 66592

static __device__ __forceinline__ uint32_t smem_u32(const void* p) {
    uint32_t a;
    asm("{ .reg .u64 t; cvta.to.shared.u64 t, %1; cvt.u32.u64 %0, t; }" : "=r"(a) : "l"(p));
    return a;
}

static __device__ __forceinline__ void ldsm4(uint32_t* r, uint32_t a) {
    asm volatile("ldmatrix.sync.aligned.m8n8.x4.shared.b16 {%0,%1,%2,%3}, [%4];"
                 : "=r"(r[0]), "=r"(r[1]), "=r"(r[2]), "=r"(r[3]) : "r"(a));
}

static __device__ __forceinline__ void sts64(uint32_t a, uint32_t v0, uint32_t v1) {
    asm volatile("st.shared.v2.b32 [%0], {%1, %2};" :: "r"(a), "r"(v0), "r"(v1));
}

static __device__ __forceinline__ void mma_f16(float* d, const uint32_t* a,
                                               uint32_t b0, uint32_t b1) {
    asm volatile(
        "mma.sync.aligned.m16n8k16.row.col.f32.f16.f16.f32 "
        "{%0,%1,%2,%3}, {%4,%5,%6,%7}, {%8,%9}, {%0,%1,%2,%3};"
        : "+f"(d[0]), "+f"(d[1]), "+f"(d[2]), "+f"(d[3])
        : "r"(a[0]), "r"(a[1]), "r"(a[2]), "r"(a[3]), "r"(b0), "r"(b1));
}

// convert one staged float4 (flat float4-index of a 64x128 tile) into A buffer
static __device__ __forceinline__ void cvt_sts_x(uint32_t xb, int idx4, float4 v) {
    const int row = idx4 >> 5;          // 0..63
    const int cg  = idx4 & 31;
    uint32_t h0, h1;
    asm("cvt.rn.f16x2.f32 %0, %1, %2;" : "=r"(h0) : "f"(v.y), "f"(v.x));
    asm("cvt.rn.f16x2.f32 %0, %1, %2;" : "=r"(h1) : "f"(v.w), "f"(v.z));
    const uint32_t a = xb + (uint32_t)row * 256 +
                       ((uint32_t)(((cg >> 1) ^ (row & 7)) << 4)) + ((cg & 1) << 3);
    sts64(a, h0, h1);
}

__global__ void __launch_bounds__(256, 1)
hyper_kernel(const float* __restrict__ xg, const float* __restrict__ wg,
             const float* __restrict__ bg, float* __restrict__ out) {
    extern __shared__ __align__(16) char smem[];
    const uint32_t sb = smem_u32(smem);
    const int tid  = threadIdx.x;
    const int lane = tid & 31;
    const int wid  = tid >> 5;
    const int wm   = wid >> 2;           // 0..1 : rows wm*32 .. +31
    const int wn   = wid & 3;            // 0..3 : cols wn*64 .. +63
    const int bid  = blockIdx.x;

    // bias -> smem
    reinterpret_cast<float*>(smem + SM_BIAS)[tid] = bg[tid];

    const float4* xg4 = reinterpret_cast<const float4*>(xg);

    // prefetch tile 0 (overlaps W init)
    float4 st0[8];
    {
        const size_t b4 = (size_t)bid * (TILE_M * 32);
        #pragma unroll
        for (int it = 0; it < 8; it++) st0[it] = xg4[b4 + tid + it * 256];
    }

    // W: fp32 -> fp16, swizzled staging in smem [n][k] 256B rows
    {
        const float4* w4 = reinterpret_cast<const float4*>(wg);
        #pragma unroll 4
        for (int i = tid; i < ODIM * 32; i += 256) {
            const int n  = i >> 5;
            const int cg = i & 31;
            float4 v = w4[i];
            uint32_t p0, p1;
            asm("cvt.rn.f16x2.f32 %0, %1, %2;" : "=r"(p0) : "f"(v.y), "f"(v.x));
            asm("cvt.rn.f16x2.f32 %0, %1, %2;" : "=r"(p1) : "f"(v.w), "f"(v.z));
            const uint32_t a = sb + SM_W + (uint32_t)n * 256 +
                               ((uint32_t)(((cg >> 1) ^ (n & 7)) << 4)) + ((cg & 1) << 3);
            sts64(a, p0, p1);
        }
    }
    __syncthreads();

    // ---- B fragments -> registers (persistent) ----
    const uint32_t lx  = (uint32_t)(lane & 7);
    const uint32_t khA = (uint32_t)((lane >> 4) & 1);
    const uint32_t khB = (uint32_t)((lane >> 3) & 1);
    uint32_t breg[8][8][2];
    {
        const uint32_t preB = sb + SM_W +
            (uint32_t)(wn * 64 + (lane & 7) + ((lane & 16) ? 8 : 0)) * 256;
        #pragma unroll
        for (int ks = 0; ks < 8; ks++) {
            const uint32_t swB = ((((uint32_t)ks << 1) | khB) ^ lx) << 4;
            #pragma unroll
            for (int np = 0; np < 4; np++) {
                uint32_t t[4];
                ldsm4(t, preB + ((uint32_t)np << 12) + swB);
                breg[ks][2 * np][0]     = t[0];
                breg[ks][2 * np][1]     = t[1];
                breg[ks][2 * np + 1][0] = t[2];
                breg[ks][2 * np + 1][1] = t[3];
            }
        }
    }
    __syncthreads();   // all warps done reading W before A buffers overwrite it

    // tile 0 -> A buffer 0
    #pragma unroll
    for (int it = 0; it < 8; it++) cvt_sts_x(sb + SM_A0, tid + it * 256, st0[it]);
    __syncthreads();

    float acc[2][8][4];
    #pragma unroll
    for (int mt = 0; mt < 2; mt++)
        #pragma unroll
        for (int nt = 0; nt < 8; nt++)
            #pragma unroll
            for (int q = 0; q < 4; q++) acc[mt][nt][q] = 0.0f;

    const uint32_t arow_off =
        (uint32_t)(wm * 32 + (lane & 7) + ((lane & 8) ? 8 : 0)) * 256;
    const float* bs = reinterpret_cast<const float*>(smem + SM_BIAS);
    const int my_n = (NTILES - bid + GRID - 1) / GRID;

    for (int tt = 0; tt < my_n; tt++) {
        const int tile = bid + tt * GRID;
        const uint32_t xb  = sb + ((tt & 1) ? SM_A1 : SM_A0);
        const uint32_t nxb = sb + ((tt & 1) ? SM_A0 : SM_A1);
        const bool more = (tt + 1 < my_n);
        const size_t nb4 = more ? ((size_t)(tile + GRID) * (TILE_M * 32)) : 0;

        float4 s0[4];
        if (more) {
            #pragma unroll
            for (int it = 0; it < 4; it++) s0[it] = xg4[nb4 + tid + it * 256];
        }

        #pragma unroll
        for (int ks = 0; ks < 4; ks++) {
            const uint32_t swA = ((((uint32_t)ks << 1) | khA) ^ lx) << 4;
            uint32_t ah[2][4];
            ldsm4(ah[0], xb + arow_off + swA);
            ldsm4(ah[1], xb + arow_off + 4096 + swA);
            #pragma unroll
            for (int np = 0; np < 4; np++) {
                #pragma unroll
                for (int mt = 0; mt < 2; mt++) {
                    mma_f16(acc[mt][2 * np],     ah[mt], breg[ks][2 * np][0],     breg[ks][2 * np][1]);
                    mma_f16(acc[mt][2 * np + 1], ah[mt], breg[ks][2 * np + 1][0], breg[ks][2 * np + 1][1]);
                }
            }
        }

        float4 s1[4];
        if (more) {
            #pragma unroll
            for (int it = 0; it < 4; it++) cvt_sts_x(nxb, tid + it * 256, s0[it]);
            #pragma unroll
            for (int it = 0; it < 4; it++) s1[it] = xg4[nb4 + 1024 + tid + it * 256];
        }

        #pragma unroll
        for (int ks = 4; ks < 8; ks++) {
            const uint32_t swA = ((((uint32_t)ks << 1) | khA) ^ lx) << 4;
            uint32_t ah[2][4];
            ldsm4(ah[0], xb + arow_off + swA);
            ldsm4(ah[1], xb + arow_off + 4096 + swA);
            #pragma unroll
            for (int np = 0; np < 4; np++) {
                #pragma unroll
                for (int mt = 0; mt < 2; mt++) {
                    mma_f16(acc[mt][2 * np],     ah[mt], breg[ks][2 * np][0],     breg[ks][2 * np][1]);
                    mma_f16(acc[mt][2 * np + 1], ah[mt], breg[ks][2 * np + 1][0], breg[ks][2 * np + 1][1]);
                }
            }
        }

        if (more) {
            #pragma unroll
            for (int it = 0; it < 4; it++) cvt_sts_x(nxb, 1024 + tid + it * 256, s1[it]);
        }

        // epilogue: add bias, square, store; zero acc
        {
            const size_t m0 = (size_t)tile * TILE_M;
            #pragma unroll
            for (int mt = 0; mt < 2; mt++) {
                const size_t rr = m0 + (size_t)(wm * 32 + mt * 16 + (lane >> 2));
                #pragma unroll
                for (int nt = 0; nt < 8; nt++) {
                    const int cc = wn * 64 + nt * 8 + (lane & 3) * 2;
                    float2 bv = *reinterpret_cast<const float2*>(bs + cc);
                    float z0 = acc[mt][nt][0] + bv.x;
                    float z1 = acc[mt][nt][1] + bv.y;
                    float z2 = acc[mt][nt][2] + bv.x;
                    float z3 = acc[mt][nt][3] + bv.y;
                    float2 o0, o1;
                    o0.x = z0 * z0; o0.y = z1 * z1;
                    o1.x = z2 * z2; o1.y = z3 * z3;
                    *reinterpret_cast<float2*>(out + rr * ODIM + cc) = o0;
                    *reinterpret_cast<float2*>(out + (rr + 8) * ODIM + cc) = o1;
                    acc[mt][nt][0] = 0.0f; acc[mt][nt][1] = 0.0f;
                    acc[mt][nt][2] = 0.0f; acc[mt][nt][3] = 0.0f;
                }
            }
        }

        __syncthreads();
    }
}

extern "C" void kernel_launch(void* const* d_in, const int* in_sizes, int n_in,
                              void* d_out, int out_size) {
    const float* x = (const float*)d_in[0];
    const float* w = (const float*)d_in[1];
    const float* b = (const float*)d_in[2];
    float* out = (float*)d_out;

    cudaFuncSetAttribute(hyper_kernel, cudaFuncAttributeMaxDynamicSharedMemorySize, SM_TOTAL);
    hyper_kernel<<<GRID, 256, SM_TOTAL>>>(x, w, b, out);
}

// round 6
// speedup vs baseline: 1.2546x; 1.0330x over previous
#include <cuda_runtime.h>
#include <cuda_fp16.h>
#include <cstdint>

// out[B,256] = (x[B,128] @ W[256,128]^T + bias)^2
// Single-term fp16 mma.sync GEMM, fp32 accum. rel_err ~3.5e-4 (calibrated).
// B fragments from smem each k-step (no breg) -> ~120 regs -> 2 CTAs/SM.

#define DDIM   128
#define ODIM   256
#define TILE_M 64
#define NTILES 2048
#define GRID   296

// smem (bytes), per CTA
#define SM_W     0            // W fp16 [256][128] swizzled, 65536
#define SM_A0    65536        // A buf 0: 64x128 fp16, 16384
#define SM_A1    81920        // A buf 1
#define SM_BIAS  98304
#define SM_TOTAL 99328

static __device__ __forceinline__ uint32_t smem_u32(const void* p) {
    uint32_t a;
    asm("{ .reg .u64 t; cvta.to.shared.u64 t, %1; cvt.u32.u64 %0, t; }" : "=r"(a) : "l"(p));
    return a;
}

static __device__ __forceinline__ void ldsm4(uint32_t* r, uint32_t a) {
    asm volatile("ldmatrix.sync.aligned.m8n8.x4.shared.b16 {%0,%1,%2,%3}, [%4];"
                 : "=r"(r[0]), "=r"(r[1]), "=r"(r[2]), "=r"(r[3]) : "r"(a));
}

static __device__ __forceinline__ void sts64(uint32_t a, uint32_t v0, uint32_t v1) {
    asm volatile("st.shared.v2.b32 [%0], {%1, %2};" :: "r"(a), "r"(v0), "r"(v1));
}

static __device__ __forceinline__ void mma_f16(float* d, const uint32_t* a,
                                               uint32_t b0, uint32_t b1) {
    asm volatile(
        "mma.sync.aligned.m16n8k16.row.col.f32.f16.f16.f32 "
        "{%0,%1,%2,%3}, {%4,%5,%6,%7}, {%8,%9}, {%0,%1,%2,%3};"
        : "+f"(d[0]), "+f"(d[1]), "+f"(d[2]), "+f"(d[3])
        : "r"(a[0]), "r"(a[1]), "r"(a[2]), "r"(a[3]), "r"(b0), "r"(b1));
}

// convert one staged float4 (flat float4-index of a 64x128 tile) into A buffer
static __device__ __forceinline__ void cvt_sts_x(uint32_t xb, int idx4, float4 v) {
    const int row = idx4 >> 5;          // 0..63
    const int cg  = idx4 & 31;
    uint32_t h0, h1;
    asm("cvt.rn.f16x2.f32 %0, %1, %2;" : "=r"(h0) : "f"(v.y), "f"(v.x));
    asm("cvt.rn.f16x2.f32 %0, %1, %2;" : "=r"(h1) : "f"(v.w), "f"(v.z));
    const uint32_t a = xb + (uint32_t)row * 256 +
                       ((uint32_t)(((cg >> 1) ^ (row & 7)) << 4)) + ((cg & 1) << 3);
    sts64(a, h0, h1);
}

__global__ void __launch_bounds__(256, 2)
hyper_kernel(const float* __restrict__ xg, const float* __restrict__ wg,
             const float* __restrict__ bg, float* __restrict__ out) {
    extern __shared__ __align__(16) char smem[];
    const uint32_t sb = smem_u32(smem);
    const int tid  = threadIdx.x;
    const int lane = tid & 31;
    const int wid  = tid >> 5;
    const int wm   = wid >> 2;           // 0..1 : rows wm*32 .. +31
    const int wn   = wid & 3;            // 0..3 : cols wn*64 .. +63
    const int bid  = blockIdx.x;

    // bias -> smem
    reinterpret_cast<float*>(smem + SM_BIAS)[tid] = bg[tid];

    const float4* xg4 = reinterpret_cast<const float4*>(xg);

    // prefetch tile 0 (overlaps W init)
    float4 st0[8];
    {
        const size_t b4 = (size_t)bid * (TILE_M * 32);
        #pragma unroll
        for (int it = 0; it < 8; it++) st0[it] = xg4[b4 + tid + it * 256];
    }

    // W: fp32 -> fp16, swizzled smem [n][k], 256B rows (persistent)
    {
        const float4* w4 = reinterpret_cast<const float4*>(wg);
        #pragma unroll 4
        for (int i = tid; i < ODIM * 32; i += 256) {
            const int n  = i >> 5;
            const int cg = i & 31;
            float4 v = w4[i];
            uint32_t p0, p1;
            asm("cvt.rn.f16x2.f32 %0, %1, %2;" : "=r"(p0) : "f"(v.y), "f"(v.x));
            asm("cvt.rn.f16x2.f32 %0, %1, %2;" : "=r"(p1) : "f"(v.w), "f"(v.z));
            const uint32_t a = sb + SM_W + (uint32_t)n * 256 +
                               ((uint32_t)(((cg >> 1) ^ (n & 7)) << 4)) + ((cg & 1) << 3);
            sts64(a, p0, p1);
        }
    }

    // tile 0 -> A buffer 0
    #pragma unroll
    for (int it = 0; it < 8; it++) cvt_sts_x(sb + SM_A0, tid + it * 256, st0[it]);
    __syncthreads();

    float acc[2][8][4];
    #pragma unroll
    for (int mt = 0; mt < 2; mt++)
        #pragma unroll
        for (int nt = 0; nt < 8; nt++)
            #pragma unroll
            for (int q = 0; q < 4; q++) acc[mt][nt][q] = 0.0f;

    const uint32_t lx  = (uint32_t)(lane & 7);
    const uint32_t khA = (uint32_t)((lane >> 4) & 1);
    const uint32_t khB = (uint32_t)((lane >> 3) & 1);
    const uint32_t arow_off =
        (uint32_t)(wm * 32 + (lane & 7) + ((lane & 8) ? 8 : 0)) * 256;
    const uint32_t preB = sb + SM_W +
        (uint32_t)(wn * 64 + (lane & 7) + ((lane & 16) ? 8 : 0)) * 256;
    const float* bs = reinterpret_cast<const float*>(smem + SM_BIAS);
    const int my_n = (NTILES - bid + GRID - 1) / GRID;

    for (int tt = 0; tt < my_n; tt++) {
        const int tile = bid + tt * GRID;
        const uint32_t xb  = sb + ((tt & 1) ? SM_A1 : SM_A0);
        const uint32_t nxb = sb + ((tt & 1) ? SM_A0 : SM_A1);
        const bool more = (tt + 1 < my_n);
        const size_t nb4 = more ? ((size_t)(tile + GRID) * (TILE_M * 32)) : 0;

        float4 s0[4];
        if (more) {
            #pragma unroll
            for (int it = 0; it < 4; it++) s0[it] = xg4[nb4 + tid + it * 256];
        }

        #pragma unroll
        for (int ks = 0; ks < 4; ks++) {
            const uint32_t swA = ((((uint32_t)ks << 1) | khA) ^ lx) << 4;
            const uint32_t swB = ((((uint32_t)ks << 1) | khB) ^ lx) << 4;
            uint32_t ah[2][4];
            ldsm4(ah[0], xb + arow_off + swA);
            ldsm4(ah[1], xb + arow_off + 4096 + swA);
            uint32_t bf[4][4];
            #pragma unroll
            for (int np = 0; np < 4; np++)
                ldsm4(bf[np], preB + ((uint32_t)np << 12) + swB);
            #pragma unroll
            for (int np = 0; np < 4; np++) {
                #pragma unroll
                for (int mt = 0; mt < 2; mt++) {
                    mma_f16(acc[mt][2 * np],     ah[mt], bf[np][0], bf[np][1]);
                    mma_f16(acc[mt][2 * np + 1], ah[mt], bf[np][2], bf[np][3]);
                }
            }
        }

        float4 s1[4];
        if (more) {
            #pragma unroll
            for (int it = 0; it < 4; it++) cvt_sts_x(nxb, tid + it * 256, s0[it]);
            #pragma unroll
            for (int it = 0; it < 4; it++) s1[it] = xg4[nb4 + 1024 + tid + it * 256];
        }

        #pragma unroll
        for (int ks = 4; ks < 8; ks++) {
            const uint32_t swA = ((((uint32_t)ks << 1) | khA) ^ lx) << 4;
            const uint32_t swB = ((((uint32_t)ks << 1) | khB) ^ lx) << 4;
            uint32_t ah[2][4];
            ldsm4(ah[0], xb + arow_off + swA);
            ldsm4(ah[1], xb + arow_off + 4096 + swA);
            uint32_t bf[4][4];
            #pragma unroll
            for (int np = 0; np < 4; np++)
                ldsm4(bf[np], preB + ((uint32_t)np << 12) + swB);
            #pragma unroll
            for (int np = 0; np < 4; np++) {
                #pragma unroll
                for (int mt = 0; mt < 2; mt++) {
                    mma_f16(acc[mt][2 * np],     ah[mt], bf[np][0], bf[np][1]);
                    mma_f16(acc[mt][2 * np + 1], ah[mt], bf[np][2], bf[np][3]);
                }
            }
        }

        if (more) {
            #pragma unroll
            for (int it = 0; it < 4; it++) cvt_sts_x(nxb, 1024 + tid + it * 256, s1[it]);
        }

        // epilogue: add bias, square, store; zero acc
        {
            const size_t m0 = (size_t)tile * TILE_M;
            #pragma unroll
            for (int mt = 0; mt < 2; mt++) {
                const size_t rr = m0 + (size_t)(wm * 32 + mt * 16 + (lane >> 2));
                #pragma unroll
                for (int nt = 0; nt < 8; nt++) {
                    const int cc = wn * 64 + nt * 8 + (lane & 3) * 2;
                    float2 bv = *reinterpret_cast<const float2*>(bs + cc);
                    float z0 = acc[mt][nt][0] + bv.x;
                    float z1 = acc[mt][nt][1] + bv.y;
                    float z2 = acc[mt][nt][2] + bv.x;
                    float z3 = acc[mt][nt][3] + bv.y;
                    float2 o0, o1;
                    o0.x = z0 * z0; o0.y = z1 * z1;
                    o1.x = z2 * z2; o1.y = z3 * z3;
                    *reinterpret_cast<float2*>(out + rr * ODIM + cc) = o0;
                    *reinterpret_cast<float2*>(out + (rr + 8) * ODIM + cc) = o1;
                    acc[mt][nt][0] = 0.0f; acc[mt][nt][1] = 0.0f;
                    acc[mt][nt][2] = 0.0f; acc[mt][nt][3] = 0.0f;
                }
            }
        }

        __syncthreads();
    }
}

extern "C" void kernel_launch(void* const* d_in, const int* in_sizes, int n_in,
                              void* d_out, int out_size) {
    const float* x = (const float*)d_in[0];
    const float* w = (const float*)d_in[1];
    const float* b = (const float*)d_in[2];
    float* out = (float*)d_out;

    cudaFuncSetAttribute(hyper_kernel, cudaFuncAttributeMaxDynamicSharedMemorySize, SM_TOTAL);
    hyper_kernel<<<GRID, 256, SM_TOTAL>>>(x, w, b, out);
}

// round 7
// speedup vs baseline: 1.2765x; 1.0174x over previous
#include <cuda_runtime.h>
#include <cuda_fp16.h>
#include <cstdint>

// out[B,256] = (x[B,128] @ W[256,128]^T + bias)^2
// Single-term fp16 mma.sync GEMM, fp32 accum. rel_err ~3.5e-4 (calibrated).
// 2 CTAs/SM; epilogue staged through smem for coalesced STG.128.

#define DDIM   128
#define ODIM   256
#define TILE_M 64
#define NTILES 2048
#define GRID   296

// smem (bytes), per CTA
#define SM_W     0            // W fp16 [256][128] swizzled, 65536
#define SM_A0    65536        // A buf 0: 64x128 fp16, 16384 (aliased as epilogue staging)
#define SM_A1    81920        // A buf 1
#define SM_BIAS  98304
#define SM_TOTAL 99328

static __device__ __forceinline__ uint32_t smem_u32(const void* p) {
    uint32_t a;
    asm("{ .reg .u64 t; cvta.to.shared.u64 t, %1; cvt.u32.u64 %0, t; }" : "=r"(a) : "l"(p));
    return a;
}

static __device__ __forceinline__ void ldsm4(uint32_t* r, uint32_t a) {
    asm volatile("ldmatrix.sync.aligned.m8n8.x4.shared.b16 {%0,%1,%2,%3}, [%4];"
                 : "=r"(r[0]), "=r"(r[1]), "=r"(r[2]), "=r"(r[3]) : "r"(a));
}

static __device__ __forceinline__ void sts64(uint32_t a, uint32_t v0, uint32_t v1) {
    asm volatile("st.shared.v2.b32 [%0], {%1, %2};" :: "r"(a), "r"(v0), "r"(v1));
}

static __device__ __forceinline__ void lds128(float* v, uint32_t a) {
    asm volatile("ld.shared.v4.f32 {%0,%1,%2,%3}, [%4];"
                 : "=f"(v[0]), "=f"(v[1]), "=f"(v[2]), "=f"(v[3]) : "r"(a));
}

static __device__ __forceinline__ void mma_f16(float* d, const uint32_t* a,
                                               uint32_t b0, uint32_t b1) {
    asm volatile(
        "mma.sync.aligned.m16n8k16.row.col.f32.f16.f16.f32 "
        "{%0,%1,%2,%3}, {%4,%5,%6,%7}, {%8,%9}, {%0,%1,%2,%3};"
        : "+f"(d[0]), "+f"(d[1]), "+f"(d[2]), "+f"(d[3])
        : "r"(a[0]), "r"(a[1]), "r"(a[2]), "r"(a[3]), "r"(b0), "r"(b1));
}

// convert one staged float4 (flat float4-index of a 64x128 tile) into A buffer
static __device__ __forceinline__ void cvt_sts_x(uint32_t xb, int idx4, float4 v) {
    const int row = idx4 >> 5;          // 0..63
    const int cg  = idx4 & 31;
    uint32_t h0, h1;
    asm("cvt.rn.f16x2.f32 %0, %1, %2;" : "=r"(h0) : "f"(v.y), "f"(v.x));
    asm("cvt.rn.f16x2.f32 %0, %1, %2;" : "=r"(h1) : "f"(v.w), "f"(v.z));
    const uint32_t a = xb + (uint32_t)row * 256 +
                       ((uint32_t)(((cg >> 1) ^ (row & 7)) << 4)) + ((cg & 1) << 3);
    sts64(a, h0, h1);
}

__global__ void __launch_bounds__(256, 2)
hyper_kernel(const float* __restrict__ xg, const float* __restrict__ wg,
             const float* __restrict__ bg, float* __restrict__ out) {
    extern __shared__ __align__(16) char smem[];
    const uint32_t sb = smem_u32(smem);
    const int tid  = threadIdx.x;
    const int lane = tid & 31;
    const int wid  = tid >> 5;
    const int wm   = wid >> 2;           // 0..1 : rows wm*32 .. +31
    const int wn   = wid & 3;            // 0..3 : cols wn*64 .. +63
    const int bid  = blockIdx.x;

    // bias -> smem
    reinterpret_cast<float*>(smem + SM_BIAS)[tid] = bg[tid];

    const float4* xg4 = reinterpret_cast<const float4*>(xg);

    // prefetch tile 0 (overlaps W init)
    float4 st0[8];
    {
        const size_t b4 = (size_t)bid * (TILE_M * 32);
        #pragma unroll
        for (int it = 0; it < 8; it++) st0[it] = xg4[b4 + tid + it * 256];
    }

    // W: fp32 -> fp16, swizzled smem [n][k], 256B rows (persistent)
    {
        const float4* w4 = reinterpret_cast<const float4*>(wg);
        #pragma unroll 4
        for (int i = tid; i < ODIM * 32; i += 256) {
            const int n  = i >> 5;
            const int cg = i & 31;
            float4 v = w4[i];
            uint32_t p0, p1;
            asm("cvt.rn.f16x2.f32 %0, %1, %2;" : "=r"(p0) : "f"(v.y), "f"(v.x));
            asm("cvt.rn.f16x2.f32 %0, %1, %2;" : "=r"(p1) : "f"(v.w), "f"(v.z));
            const uint32_t a = sb + SM_W + (uint32_t)n * 256 +
                               ((uint32_t)(((cg >> 1) ^ (n & 7)) << 4)) + ((cg & 1) << 3);
            sts64(a, p0, p1);
        }
    }

    // tile 0 -> A buffer 0
    #pragma unroll
    for (int it = 0; it < 8; it++) cvt_sts_x(sb + SM_A0, tid + it * 256, st0[it]);
    __syncthreads();

    float acc[2][8][4];
    #pragma unroll
    for (int mt = 0; mt < 2; mt++)
        #pragma unroll
        for (int nt = 0; nt < 8; nt++)
            #pragma unroll
            for (int q = 0; q < 4; q++) acc[mt][nt][q] = 0.0f;

    const uint32_t lx  = (uint32_t)(lane & 7);
    const uint32_t khA = (uint32_t)((lane >> 4) & 1);
    const uint32_t khB = (uint32_t)((lane >> 3) & 1);
    const uint32_t arow_off =
        (uint32_t)(wm * 32 + (lane & 7) + ((lane & 8) ? 8 : 0)) * 256;
    const uint32_t preB = sb + SM_W +
        (uint32_t)(wn * 64 + (lane & 7) + ((lane & 16) ? 8 : 0)) * 256;
    const float* bs = reinterpret_cast<const float*>(smem + SM_BIAS);
    const int my_n = (NTILES - bid + GRID - 1) / GRID;

    for (int tt = 0; tt < my_n; tt++) {
        const int tile = bid + tt * GRID;
        const uint32_t xb  = sb + ((tt & 1) ? SM_A1 : SM_A0);
        const uint32_t nxb = sb + ((tt & 1) ? SM_A0 : SM_A1);
        const bool more = (tt + 1 < my_n);
        const size_t nb4 = more ? ((size_t)(tile + GRID) * (TILE_M * 32)) : 0;

        float4 s0[4];
        if (more) {
            #pragma unroll
            for (int it = 0; it < 4; it++) s0[it] = xg4[nb4 + tid + it * 256];
        }

        #pragma unroll
        for (int ks = 0; ks < 4; ks++) {
            const uint32_t swA = ((((uint32_t)ks << 1) | khA) ^ lx) << 4;
            const uint32_t swB = ((((uint32_t)ks << 1) | khB) ^ lx) << 4;
            uint32_t ah[2][4];
            ldsm4(ah[0], xb + arow_off + swA);
            ldsm4(ah[1], xb + arow_off + 4096 + swA);
            uint32_t bf[4][4];
            #pragma unroll
            for (int np = 0; np < 4; np++)
                ldsm4(bf[np], preB + ((uint32_t)np << 12) + swB);
            #pragma unroll
            for (int np = 0; np < 4; np++) {
                #pragma unroll
                for (int mt = 0; mt < 2; mt++) {
                    mma_f16(acc[mt][2 * np],     ah[mt], bf[np][0], bf[np][1]);
                    mma_f16(acc[mt][2 * np + 1], ah[mt], bf[np][2], bf[np][3]);
                }
            }
        }

        float4 s1[4];
        if (more) {
            #pragma unroll
            for (int it = 0; it < 4; it++) cvt_sts_x(nxb, tid + it * 256, s0[it]);
            #pragma unroll
            for (int it = 0; it < 4; it++) s1[it] = xg4[nb4 + 1024 + tid + it * 256];
        }

        #pragma unroll
        for (int ks = 4; ks < 8; ks++) {
            const uint32_t swA = ((((uint32_t)ks << 1) | khA) ^ lx) << 4;
            const uint32_t swB = ((((uint32_t)ks << 1) | khB) ^ lx) << 4;
            uint32_t ah[2][4];
            ldsm4(ah[0], xb + arow_off + swA);
            ldsm4(ah[1], xb + arow_off + 4096 + swA);
            uint32_t bf[4][4];
            #pragma unroll
            for (int np = 0; np < 4; np++)
                ldsm4(bf[np], preB + ((uint32_t)np << 12) + swB);
            #pragma unroll
            for (int np = 0; np < 4; np++) {
                #pragma unroll
                for (int mt = 0; mt < 2; mt++) {
                    mma_f16(acc[mt][2 * np],     ah[mt], bf[np][0], bf[np][1]);
                    mma_f16(acc[mt][2 * np + 1], ah[mt], bf[np][2], bf[np][3]);
                }
            }
        }

        if (more) {
            #pragma unroll
            for (int it = 0; it < 4; it++) cvt_sts_x(nxb, 1024 + tid + it * 256, s1[it]);
        }

        __syncthreads();   // all A-ldsm of xb done -> xb reusable as staging

        // ---- staged epilogue: frag -> smem (swizzled) -> coalesced STG.128 ----
        {
            // bias pairs for this thread's 8 nt slots (constant across groups)
            float2 bp[8];
            #pragma unroll
            for (int nt = 0; nt < 8; nt++)
                bp[nt] = *reinterpret_cast<const float2*>(
                    bs + wn * 64 + nt * 8 + (lane & 3) * 2);

            const uint32_t ebuf = xb + (uint32_t)wid * 2048;
            const uint32_t rl   = (uint32_t)(lane >> 2);          // 0..7
            const uint32_t sbase = ebuf + rl * 256 + ((uint32_t)(lane & 3) << 3);
            const size_t  m0 = (size_t)tile * TILE_M;
            const uint32_t c  = (uint32_t)(lane & 15);
            const uint32_t rref = (uint32_t)(lane >> 4);          // 0..1

            #pragma unroll
            for (int g = 0; g < 4; g++) {
                const int mt = g >> 1;
                const int hf = g & 1;
                #pragma unroll
                for (int nt = 0; nt < 8; nt++) {
                    float z0 = acc[mt][nt][hf * 2 + 0] + bp[nt].x;
                    float z1 = acc[mt][nt][hf * 2 + 1] + bp[nt].y;
                    sts64(sbase + (((uint32_t)nt ^ rl) << 5),
                          __float_as_uint(z0 * z0), __float_as_uint(z1 * z1));
                }
                __syncwarp();
                const size_t rowg0 = m0 + (size_t)(wm * 32 + mt * 16 + hf * 8);
                #pragma unroll
                for (int j = 0; j < 4; j++) {
                    const uint32_t r = 2 * j + rref;
                    float v[4];
                    lds128(v, ebuf + r * 256 + ((((c >> 1) ^ r) << 5)) + ((c & 1) << 4));
                    float4* dst = reinterpret_cast<float4*>(
                        out + (rowg0 + r) * ODIM + wn * 64 + c * 4);
                    dst->x = v[0]; dst->y = v[1]; dst->z = v[2]; dst->w = v[3];
                }
                __syncwarp();
            }

            #pragma unroll
            for (int mt = 0; mt < 2; mt++)
                #pragma unroll
                for (int nt = 0; nt < 8; nt++)
                    #pragma unroll
                    for (int q = 0; q < 4; q++) acc[mt][nt][q] = 0.0f;
        }

        __syncthreads();
    }
}

extern "C" void kernel_launch(void* const* d_in, const int* in_sizes, int n_in,
                              void* d_out, int out_size) {
    const float* x = (const float*)d_in[0];
    const float* w = (const float*)d_in[1];
    const float* b = (const float*)d_in[2];
    float* out = (float*)d_out;

    cudaFuncSetAttribute(hyper_kernel, cudaFuncAttributeMaxDynamicSharedMemorySize, SM_TOTAL);
    hyper_kernel<<<GRID, 256, SM_TOTAL>>>(x, w, b, out);
}